// round 13
// baseline (speedup 1.0000x reference)
#include <cuda_runtime.h>
#include <stdint.h>

#define N_POS 8192
#define N_NEG 4000u
#define N_TOT (N_POS + N_POS * (int)N_NEG)  // 32,776,192 (divisible by 8)
#define N_VEC (N_TOT / 4)                   // 8,194,048
#define N_VEC8 (N_TOT / 8)                  // 4,097,024

#define HIST_WORDS (N_POS / 2)              // 4096 packed u16x2 words

#define P2_BLOCKS 592
#define P2_THREADS 512

#define P3A_BLOCKS 32
#define P3A_THREADS 128                     // 4096 threads = one per packed word

// Scratch (allocation-free rule: __device__ globals)
__device__ float          g_pos[N_POS];
__device__ unsigned short g_rowid[N_TOT];                     // 65.55 MB
__device__ unsigned int   g_hist_all[P2_BLOCKS * HIST_WORDS]; // 9.7 MB (L2-resident)
__device__ double         g_partial[P3A_BLOCKS];

// ---------------------------------------------------------------------------
// Pass 1: scan idx (int32) once, 8 elems/iter. Emit u16 row-id per element
// (0xFFFF = pos), packed as one STG.128 per iter; scatter the 8192 pos vals.
// ---------------------------------------------------------------------------
__global__ void __launch_bounds__(256) mrr_pass1(
    const float* __restrict__ val, const int* __restrict__ idx)
{
    const unsigned int tid = blockIdx.x * blockDim.x + threadIdx.x;
    const unsigned int stride = gridDim.x * blockDim.x;

    const int4* __restrict__ idx4 = (const int4*)idx;
    uint4* __restrict__ rid8 = (uint4*)g_rowid;

    #pragma unroll 2
    for (unsigned int v = tid; v < N_VEC8; v += stride) {
        int4 qa = idx4[2 * v];
        int4 qb = idx4[2 * v + 1];
        unsigned int base = v * 8u;

        unsigned int r0, r1, r2, r3, r4, r5, r6, r7;
        unsigned int j;
        j = (unsigned)qa.x; if (j < N_POS) { r0 = 0xFFFFu; g_pos[j] = val[base + 0]; } else r0 = (j - N_POS) / N_NEG;
        j = (unsigned)qa.y; if (j < N_POS) { r1 = 0xFFFFu; g_pos[j] = val[base + 1]; } else r1 = (j - N_POS) / N_NEG;
        j = (unsigned)qa.z; if (j < N_POS) { r2 = 0xFFFFu; g_pos[j] = val[base + 2]; } else r2 = (j - N_POS) / N_NEG;
        j = (unsigned)qa.w; if (j < N_POS) { r3 = 0xFFFFu; g_pos[j] = val[base + 3]; } else r3 = (j - N_POS) / N_NEG;
        j = (unsigned)qb.x; if (j < N_POS) { r4 = 0xFFFFu; g_pos[j] = val[base + 4]; } else r4 = (j - N_POS) / N_NEG;
        j = (unsigned)qb.y; if (j < N_POS) { r5 = 0xFFFFu; g_pos[j] = val[base + 5]; } else r5 = (j - N_POS) / N_NEG;
        j = (unsigned)qb.z; if (j < N_POS) { r6 = 0xFFFFu; g_pos[j] = val[base + 6]; } else r6 = (j - N_POS) / N_NEG;
        j = (unsigned)qb.w; if (j < N_POS) { r7 = 0xFFFFu; g_pos[j] = val[base + 7]; } else r7 = (j - N_POS) / N_NEG;

        uint4 r;
        r.x = r0 | (r1 << 16);
        r.y = r2 | (r3 << 16);
        r.z = r4 | (r5 << 16);
        r.w = r6 | (r7 << 16);
        rid8[v] = r;
    }
}

// ---------------------------------------------------------------------------
// Pass 2: EXACT R4 loop (512 thr x 592 blocks, plain loads, unroll 2),
// minority-side counting:
//   p >  0 -> count (v >  p);  p <= 0 -> count (v <= p)
// inc = (v > p) XOR (p <= 0); fixed up in pass 3. ONLY change vs R4: flush is
// a plain coalesced 16KB STG to this block's private slice (zero atomics).
// 48KB static smem -> 4 blocks/SM, one wave of 592.
// ---------------------------------------------------------------------------
__global__ void __launch_bounds__(P2_THREADS) mrr_pass2(const float* __restrict__ val)
{
    __shared__ float        s_pos[N_POS];       // 32768 B
    __shared__ unsigned int s_hist[HIST_WORDS]; // 16384 B

    const int t = threadIdx.x;
    for (int i = t; i < N_POS; i += P2_THREADS)      s_pos[i]  = g_pos[i];
    for (int i = t; i < HIST_WORDS; i += P2_THREADS) s_hist[i] = 0u;
    __syncthreads();

    const unsigned int tid = blockIdx.x * P2_THREADS + t;
    const unsigned int stride = gridDim.x * P2_THREADS;
    const float4*  __restrict__ v4 = (const float4*)val;
    const ushort4* __restrict__ r4 = (const ushort4*)g_rowid;

    #pragma unroll 2
    for (unsigned int v = tid; v < N_VEC; v += stride) {
        float4  f = v4[v];
        ushort4 r = r4[v];
        {
            float p = s_pos[r.x & 0x1FFFu];
            if (r.x != 0xFFFFu && ((f.x > p) != (p <= 0.0f)))
                atomicAdd(&s_hist[r.x >> 1], 1u << ((r.x & 1u) << 4));
        }
        {
            float p = s_pos[r.y & 0x1FFFu];
            if (r.y != 0xFFFFu && ((f.y > p) != (p <= 0.0f)))
                atomicAdd(&s_hist[r.y >> 1], 1u << ((r.y & 1u) << 4));
        }
        {
            float p = s_pos[r.z & 0x1FFFu];
            if (r.z != 0xFFFFu && ((f.z > p) != (p <= 0.0f)))
                atomicAdd(&s_hist[r.z >> 1], 1u << ((r.z & 1u) << 4));
        }
        {
            float p = s_pos[r.w & 0x1FFFu];
            if (r.w != 0xFFFFu && ((f.w > p) != (p <= 0.0f)))
                atomicAdd(&s_hist[r.w >> 1], 1u << ((r.w & 1u) << 4));
        }
    }
    __syncthreads();

    // Atomic-free flush: private coalesced 16KB store.
    unsigned int* __restrict__ dst = &g_hist_all[blockIdx.x * HIST_WORDS];
    for (int i = t; i < HIST_WORDS; i += P2_THREADS)
        dst[i] = s_hist[i];
}

// ---------------------------------------------------------------------------
// Pass 3a: one thread per packed word; fixed-order u32 sum across 592 block
// histograms (L2-resident, warp-coalesced), minority fixup, sample_mrr out,
// per-block double partial.
// ---------------------------------------------------------------------------
__global__ void __launch_bounds__(P3A_THREADS) mrr_pass3a(float* __restrict__ out)
{
    __shared__ double ssum[P3A_THREADS];
    const int t = threadIdx.x;
    const int w = blockIdx.x * P3A_THREADS + t;   // packed word = rows 2w, 2w+1

    unsigned int acc = 0u;
    #pragma unroll 8
    for (int b = 0; b < P2_BLOCKS; b++)
        acc += g_hist_all[b * HIST_WORDS + w];    // halves can't carry (<=4000)

    unsigned int c0 = acc & 0xFFFFu;
    unsigned int c1 = acc >> 16;
    float p0 = g_pos[2 * w];
    float p1 = g_pos[2 * w + 1];
    unsigned int g0 = (p0 > 0.0f) ? c0 : (N_NEG - c0);
    unsigned int g1 = (p1 > 0.0f) ? c1 : (N_NEG - c1);
    float s0 = 1.0f / (float)(1u + g0);
    float s1 = 1.0f / (float)(1u + g1);
    out[1 + 2 * w]     = s0;   // out+1 only 4B-aligned: scalar stores
    out[1 + 2 * w + 1] = s1;

    ssum[t] = (double)s0 + (double)s1;
    __syncthreads();
    for (int off = P3A_THREADS / 2; off > 0; off >>= 1) {
        if (t < off) ssum[t] += ssum[t + off];
        __syncthreads();
    }
    if (t == 0) g_partial[blockIdx.x] = ssum[0];
}

// ---------------------------------------------------------------------------
// Pass 3b: deterministic fixed-order final mean.
// ---------------------------------------------------------------------------
__global__ void mrr_pass3b(float* __restrict__ out)
{
    if (threadIdx.x == 0) {
        double s = 0.0;
        #pragma unroll
        for (int i = 0; i < P3A_BLOCKS; i++) s += g_partial[i];
        out[0] = (float)(s / (double)N_POS);
    }
}

extern "C" void kernel_launch(void* const* d_in, const int* in_sizes, int n_in,
                              void* d_out, int out_size)
{
    const float* val = (const float*)d_in[0];
    const int*   idx = (const int*)d_in[1];
    float*       out = (float*)d_out;

    mrr_pass1<<<2048, 256>>>(val, idx);
    mrr_pass2<<<P2_BLOCKS, P2_THREADS>>>(val);
    mrr_pass3a<<<P3A_BLOCKS, P3A_THREADS>>>(out);
    mrr_pass3b<<<1, 32>>>(out);
}

// round 14
// speedup vs baseline: 1.1750x; 1.1750x over previous
#include <cuda_runtime.h>
#include <stdint.h>

#define N_POS 8192
#define N_NEG 4000u
#define N_TOT (N_POS + N_POS * (int)N_NEG)  // 32,776,192 (divisible by 8)
#define N_VEC (N_TOT / 4)                   // 8,194,048
#define N_VEC8 (N_TOT / 8)                  // 4,097,024

#define HIST_WORDS (N_POS / 2)              // 4096 packed u16x2 words

#define P2_BLOCKS 592
#define P2_THREADS 512

// Scratch (allocation-free rule: __device__ globals)
__device__ float          g_pos[N_POS];
__device__ unsigned short g_rowid[N_TOT];          // 65.55 MB
__device__ unsigned int   g_hist[HIST_WORDS];      // packed u16x2, unpadded (R4-proven)

// ---------------------------------------------------------------------------
// Pass 1 (EXACT R4): scan idx (int32) once. Emit u16 row-id per element
// (0xFFFF = pos), scatter the 8192 pos values, zero the histogram.
// ---------------------------------------------------------------------------
__global__ void __launch_bounds__(256) mrr_pass1(
    const float* __restrict__ val, const int* __restrict__ idx)
{
    const unsigned int tid = blockIdx.x * blockDim.x + threadIdx.x;
    if (tid < HIST_WORDS) g_hist[tid] = 0u;

    const unsigned int stride = gridDim.x * blockDim.x;
    const int4* __restrict__ idx4 = (const int4*)idx;
    ushort4* __restrict__ rid4 = (ushort4*)g_rowid;

    #pragma unroll 4
    for (unsigned int v = tid; v < N_VEC; v += stride) {
        int4 q = idx4[v];
        unsigned int j0 = (unsigned int)q.x;
        unsigned int j1 = (unsigned int)q.y;
        unsigned int j2 = (unsigned int)q.z;
        unsigned int j3 = (unsigned int)q.w;
        unsigned int base = v * 4u;

        ushort4 r;
        if (j0 < N_POS) { r.x = 0xFFFFu; g_pos[j0] = val[base + 0]; }
        else            { r.x = (unsigned short)((j0 - N_POS) / N_NEG); }
        if (j1 < N_POS) { r.y = 0xFFFFu; g_pos[j1] = val[base + 1]; }
        else            { r.y = (unsigned short)((j1 - N_POS) / N_NEG); }
        if (j2 < N_POS) { r.z = 0xFFFFu; g_pos[j2] = val[base + 2]; }
        else            { r.z = (unsigned short)((j2 - N_POS) / N_NEG); }
        if (j3 < N_POS) { r.w = 0xFFFFu; g_pos[j3] = val[base + 3]; }
        else            { r.w = (unsigned short)((j3 - N_POS) / N_NEG); }

        rid4[v] = r;
    }
}

// ---------------------------------------------------------------------------
// Pass 2: R4 config + R4 flush; ONLY change = 8 elems/iter inner loop:
// one LDG.128 (8 packed u16 rowids) + two LDG.128 (vals) -> 3 LDG per 8 elems
// instead of 4, longer independent body for ILP. Minority-side counting:
//   p >  0 -> count (v >  p);  p <= 0 -> count (v <= p)
// inc = (v > p) XOR (p <= 0); fixed up in pass 3. Per-row total <= 4000 so
// packed u16 halves never overflow. 48KB static smem -> 4 blocks/SM, 1 wave.
// ---------------------------------------------------------------------------
__device__ __forceinline__ void hist_one(
    float v, unsigned int row, const float* s_pos, unsigned int* s_hist)
{
    float p = s_pos[row & 0x1FFFu];
    if (row != 0xFFFFu && ((v > p) != (p <= 0.0f)))
        atomicAdd(&s_hist[row >> 1], 1u << ((row & 1u) << 4));
}

__global__ void __launch_bounds__(P2_THREADS) mrr_pass2(const float* __restrict__ val)
{
    __shared__ float        s_pos[N_POS];       // 32768 B
    __shared__ unsigned int s_hist[HIST_WORDS]; // 16384 B

    const int t = threadIdx.x;
    for (int i = t; i < N_POS; i += P2_THREADS)      s_pos[i]  = g_pos[i];
    for (int i = t; i < HIST_WORDS; i += P2_THREADS) s_hist[i] = 0u;
    __syncthreads();

    const unsigned int tid = blockIdx.x * P2_THREADS + t;
    const unsigned int stride = gridDim.x * P2_THREADS;
    const float4* __restrict__ v4 = (const float4*)val;
    const uint4*  __restrict__ r8 = (const uint4*)g_rowid;   // 8 u16 per load

    for (unsigned int v = tid; v < N_VEC8; v += stride) {
        uint4  rr = r8[v];
        float4 fa = v4[2 * v];
        float4 fb = v4[2 * v + 1];

        hist_one(fa.x, rr.x & 0xFFFFu, s_pos, s_hist);
        hist_one(fa.y, rr.x >> 16,     s_pos, s_hist);
        hist_one(fa.z, rr.y & 0xFFFFu, s_pos, s_hist);
        hist_one(fa.w, rr.y >> 16,     s_pos, s_hist);
        hist_one(fb.x, rr.z & 0xFFFFu, s_pos, s_hist);
        hist_one(fb.y, rr.z >> 16,     s_pos, s_hist);
        hist_one(fb.z, rr.w & 0xFFFFu, s_pos, s_hist);
        hist_one(fb.w, rr.w >> 16,     s_pos, s_hist);
    }
    __syncthreads();

    // R4-proven flush: whole-word atomic add (halves can't carry, <=4000).
    for (int i = t; i < HIST_WORDS; i += P2_THREADS) {
        unsigned int h = s_hist[i];
        if (h) atomicAdd(&g_hist[i], h);
    }
}

// ---------------------------------------------------------------------------
// Pass 3 (EXACT R4 + minority fixup): ranks -> sample_mrr, fixed-order mean.
// out[0] = mrr, out[1..8192] = sample_mrr
// ---------------------------------------------------------------------------
__global__ void __launch_bounds__(1024) mrr_pass3(float* __restrict__ out)
{
    __shared__ double ssum[1024];
    const int t = threadIdx.x;
    double local = 0.0;
    for (int r = t; r < N_POS; r += 1024) {
        unsigned int h = g_hist[r >> 1];
        unsigned int c = (r & 1) ? (h >> 16) : (h & 0xFFFFu);
        float p = g_pos[r];
        unsigned int cnt_gt = (p > 0.0f) ? c : (N_NEG - c);
        float s = 1.0f / (float)(1u + cnt_gt);
        out[1 + r] = s;
        local += (double)s;
    }
    ssum[t] = local;
    __syncthreads();
    for (int off = 512; off > 0; off >>= 1) {
        if (t < off) ssum[t] += ssum[t + off];
        __syncthreads();
    }
    if (t == 0) out[0] = (float)(ssum[0] / (double)N_POS);
}

extern "C" void kernel_launch(void* const* d_in, const int* in_sizes, int n_in,
                              void* d_out, int out_size)
{
    const float* val = (const float*)d_in[0];
    const int*   idx = (const int*)d_in[1];
    float*       out = (float*)d_out;

    mrr_pass1<<<2048, 256>>>(val, idx);
    mrr_pass2<<<P2_BLOCKS, P2_THREADS>>>(val);
    mrr_pass3<<<1, 1024>>>(out);
}